// round 11
// baseline (speedup 1.0000x reference)
#include <cuda_runtime.h>
#include <cstdint>

// CTC loss (Keras ctc_batch_cost convention, blank = C-1).
// y_true: [B, L] int32; y_pred: [B, T, C] float32 softmax probs.
// out: [B] float32 = -log P(labels | y_pred).
//
// Pure LOG-DOMAIN recursion mirroring the reference op-for-op
// (logaddexp chains, NEG_INF = -1e30), one warp per sample, 4 states/lane.
// No shared memory, no cp.async: each thread's gathered classes are fixed
// over time, so next rows are prefetched into a depth-2 REGISTER ring via
// __ldg (tensor is L2-resident across graph replays). Eliminates every
// shared suspect from R4-R9 (scaling machinery, smem ring, syncwarp
// visibility) except the recursion skeleton itself.
// [R11: resubmission of R10 — broker infra failed twice, kernel never ran.]

#define FULLMASK 0xFFFFFFFFu

constexpr int B_ = 256;
constexpr int T_ = 512;
constexpr int C_ = 128;
constexpr int L_ = 48;
constexpr int S_ = 2 * L_ + 1;   // 97
constexpr int WARPS = 4;          // samples per block (one warp per SMSP)
constexpr float EPSF   = 1e-7f;
constexpr float NEGINF = -1e30f;  // log-domain zero, as in the reference

// logaddexp(x, y) = max + log(1 + exp(-|x-y|)); exact for the -1e30 cases:
//   both -1e30 -> -1e30 + log2 (matches jnp); one -1e30 -> the finite arg.
__device__ __forceinline__ float lse2(float x, float y) {
    const float m = fmaxf(x, y);
    const float d = fabsf(x - y);
    return m + __logf(1.f + __expf(-d));
}

__global__ __launch_bounds__(WARPS * 32, 1)
void ctc_loss_kernel(const int* __restrict__ y_true,
                     const float* __restrict__ y_pred,
                     float* __restrict__ out) {
    const int lane = threadIdx.x & 31;
    const int w    = threadIdx.x >> 5;
    const int b    = blockIdx.x * WARPS + w;

    const float* prow = y_pred + (size_t)b * T_ * C_;
    const int*   lab  = y_true + b * L_;
    const int blank = C_ - 1;

    // ---- per-lane static setup: extended labels + skip flags ----
    // lane holds extended states s = 4*lane .. 4*lane+3:
    //   s=4l   : blank            s=4l+1 : label[2l]
    //   s=4l+2 : blank            s=4l+3 : label[2l+1]
    const int k1 = 2 * lane;
    const int k3 = 2 * lane + 1;
    const int lab1  = (k1 < L_) ? lab[k1] : blank;
    const int lab3  = (k3 < L_) ? lab[k3] : blank;
    const int labm1 = (k1 >= 1 && k1 - 1 < L_) ? lab[k1 - 1] : blank;
    const int cls1 = lab1 & (C_ - 1);
    const int cls3 = lab3 & (C_ - 1);
    // can_skip(s) = ext[s] != blank && ext[s] != ext[s-2]  (ext[-1] = blank)
    const bool can1 = (lab1 != blank) && (lane == 0 || lab1 != labm1);
    const bool can3 = (lab3 != blank) && (lab3 != lab1);

    // label length = count_nonzero(y_true[b])
    const unsigned bl0 = __ballot_sync(FULLMASK, lab[lane] != 0);  // lanes 0..31 < L
    const unsigned bl1 = __ballot_sync(FULLMASK,
                          (lane + 32 < L_) ? (lab[lane + 32] != 0) : false);
    const int len = __popc(bl0) + __popc(bl1);

    // ---- t = 0 init: alpha[0] = lp[0,0], alpha[1] = lp[0,1], rest NEG_INF ----
    float la0 = NEGINF, la1 = NEGINF, la2 = NEGINF, la3 = NEGINF;
    if (lane == 0) {
        la0 = __logf(__ldg(prow + blank) + EPSF);
        la1 = __logf(__ldg(prow + cls1)  + EPSF);
    }

    // ---- register prefetch ring, depth 2 (classes fixed per thread) ----
    float pbr[2], p1r[2], p3r[2];
    {
        const float* r1 = prow + 1 * C_;
        const float* r2 = prow + 2 * C_;
        pbr[1] = __ldg(r1 + blank); p1r[1] = __ldg(r1 + cls1); p3r[1] = __ldg(r1 + cls3);
        pbr[0] = __ldg(r2 + blank); p1r[0] = __ldg(r2 + cls1); p3r[0] = __ldg(r2 + cls3);
    }

    for (int t = 1; t < T_; ++t) {
        const int sl = t & 1;
        const float pb = pbr[sl], p1 = p1r[sl], p3 = p3r[sl];
        if (t + 2 < T_) {   // issue loads for t+2 (consumed two steps later)
            const float* rp = prow + (size_t)(t + 2) * C_;
            pbr[sl] = __ldg(rp + blank);
            p1r[sl] = __ldg(rp + cls1);
            p3r[sl] = __ldg(rp + cls3);
        }

        const float lpb = __logf(pb + EPSF);
        const float lp1 = __logf(p1 + EPSF);
        const float lp3 = __logf(p3 + EPSF);

        float prev3 = __shfl_up_sync(FULLMASK, la3, 1);   // alpha[4l-1]
        if (lane == 0) prev3 = NEGINF;

        const float sk1 = can1 ? prev3 : NEGINF;   // skip into s=4l+1 from s=4l-1
        const float sk3 = can3 ? la1   : NEGINF;   // skip into s=4l+3 from s=4l+1

        const float n0 = lse2(la0, prev3)            + lpb;
        const float n1 = lse2(lse2(la1, la0), sk1)   + lp1;
        const float n2 = lse2(la2, la1)              + lpb;
        const float n3 = lse2(lse2(la3, la2), sk3)   + lp3;
        la0 = n0; la1 = n1; la2 = n2; la3 = n3;
        // states s >= S only ever pollute upward (never read by valid states);
        // final readout touches s = 95, 96 only, so no masks needed.
    }

    // ---- final: loss = -logaddexp(alpha[2*len], alpha[2*len - 1]) ----
    int end = 2 * len;
    if (end > S_ - 1) end = S_ - 1;
    int pen = end - 1;
    if (pen < 0) pen = 0;
    // gather alpha[s]: lane s>>2, register s&3 (end/pen uniform per warp)
    const int re = end & 3, rp_ = pen & 3;
    const float ve_all = (re == 0) ? la0 : (re == 1) ? la1 : (re == 2) ? la2 : la3;
    const float vp_all = (rp_ == 0) ? la0 : (rp_ == 1) ? la1 : (rp_ == 2) ? la2 : la3;
    const float ve = __shfl_sync(FULLMASK, ve_all, end >> 2);
    const float vp = __shfl_sync(FULLMASK, vp_all, pen >> 2);
    if (lane == 0) {
        const float m = fmaxf(ve, vp);
        out[b] = -(m + log1pf(expf(-fabsf(ve - vp))));
    }
}

extern "C" void kernel_launch(void* const* d_in, const int* in_sizes, int n_in,
                              void* d_out, int out_size) {
    const int* y_true;
    const float* y_pred;
    if (in_sizes[0] == B_ * L_) {
        y_true = (const int*)d_in[0];
        y_pred = (const float*)d_in[1];
    } else {
        y_true = (const int*)d_in[1];
        y_pred = (const float*)d_in[0];
    }
    ctc_loss_kernel<<<B_ / WARPS, WARPS * 32>>>(y_true, y_pred, (float*)d_out);
}

// round 13
// speedup vs baseline: 1.1688x; 1.1688x over previous
#include <cuda_runtime.h>
#include <cstdint>

// CTC loss (Keras ctc_batch_cost convention, blank = C-1).
// y_true: [B, L] int32; y_pred: [B, T, C] float32 softmax probs.
// out: [B] float32 = -log P(labels | y_pred).
//
// Grouped-LSE log2-domain recursion. One warp/sample, 4 states/lane.
// Per step, ONE per-lane normalization m = max(a0..a3, prev3), shared exps,
// and the row log folded into the state log via the product:
//   a_i' = lg2( (sum_j ex2(a_j - m)) * (p_i + eps) ) + m
// Exactly the reference recursion, regrouped: 9 MUFU/step (was 15), chain
// ~82 cyc (was ~130+). Register prefetch ring depth 4, unroll x4.
// [R13: resubmission of R12 — broker infra failed twice, kernel never ran.]

#define FULLMASK 0xFFFFFFFFu

constexpr int B_ = 256;
constexpr int T_ = 512;
constexpr int C_ = 128;
constexpr int L_ = 48;
constexpr int S_ = 2 * L_ + 1;   // 97
constexpr int WARPS = 4;          // samples per block
constexpr float EPSF   = 1e-7f;
constexpr float NEGINF = -1e30f;  // log-domain zero (finite, like reference)
constexpr float TINYF  = 1e-30f;  // sum floor: keeps states finite (no -inf/NaN)

__device__ __forceinline__ float ex2(float x) {
    float r; asm("ex2.approx.f32 %0, %1;" : "=f"(r) : "f"(x)); return r;
}
__device__ __forceinline__ float lg2(float x) {
    float r; asm("lg2.approx.f32 %0, %1;" : "=f"(r) : "f"(x)); return r;
}

__global__ __launch_bounds__(WARPS * 32, 1)
void ctc_loss_kernel(const int* __restrict__ y_true,
                     const float* __restrict__ y_pred,
                     float* __restrict__ out) {
    const int lane = threadIdx.x & 31;
    const int w    = threadIdx.x >> 5;
    const int b    = blockIdx.x * WARPS + w;

    const float* prow = y_pred + (size_t)b * T_ * C_;
    const int*   lab  = y_true + b * L_;
    const int blank = C_ - 1;

    // ---- per-lane static setup: extended labels + skip flags ----
    // lane holds extended states s = 4*lane .. 4*lane+3:
    //   s=4l: blank   s=4l+1: label[2l]   s=4l+2: blank   s=4l+3: label[2l+1]
    const int k1 = 2 * lane;
    const int k3 = 2 * lane + 1;
    const int lab1  = (k1 < L_) ? lab[k1] : blank;
    const int lab3  = (k3 < L_) ? lab[k3] : blank;
    const int labm1 = (k1 >= 1 && k1 - 1 < L_) ? lab[k1 - 1] : blank;
    const int cls1 = lab1 & (C_ - 1);
    const int cls3 = lab3 & (C_ - 1);
    // can_skip(s) = ext[s] != blank && ext[s] != ext[s-2]  (ext[-1] = blank)
    const float c1f = ((lab1 != blank) && (lane == 0 || lab1 != labm1)) ? 1.f : 0.f;
    const float c3f = ((lab3 != blank) && (lab3 != lab1)) ? 1.f : 0.f;

    // label length = count_nonzero(y_true[b])
    const unsigned bl0 = __ballot_sync(FULLMASK, lab[lane] != 0);  // lanes 0..31 < L
    const unsigned bl1 = __ballot_sync(FULLMASK,
                          (lane + 32 < L_) ? (lab[lane + 32] != 0) : false);
    const int len = __popc(bl0) + __popc(bl1);

    // ---- t = 0 init (log2 domain) ----
    float la0 = NEGINF, la1 = NEGINF, la2 = NEGINF, la3 = NEGINF;
    if (lane == 0) {
        la0 = lg2(__ldg(prow + blank) + EPSF);
        la1 = lg2(__ldg(prow + cls1)  + EPSF);
    }

    // ---- register prefetch ring, depth 4 (classes fixed per thread) ----
    // slot = t & 3; prologue loads rows t = 1..4 into slots 1,2,3,0.
    float pbr[4], p1r[4], p3r[4];
    #pragma unroll
    for (int i = 1; i <= 4; ++i) {
        const float* r = prow + (size_t)i * C_;
        pbr[i & 3] = __ldg(r + blank);
        p1r[i & 3] = __ldg(r + cls1);
        p3r[i & 3] = __ldg(r + cls3);
    }

#define CTC_STEP(T_IDX, SLOT)                                                  \
    {                                                                          \
        const float pbe = pbr[SLOT] + EPSF;                                    \
        const float p1e = p1r[SLOT] + EPSF;                                    \
        const float p3e = p3r[SLOT] + EPSF;                                    \
        if ((T_IDX) + 4 < T_) {                                                \
            const float* rp = prow + (size_t)((T_IDX) + 4) * C_;               \
            pbr[SLOT] = __ldg(rp + blank);                                     \
            p1r[SLOT] = __ldg(rp + cls1);                                      \
            p3r[SLOT] = __ldg(rp + cls3);                                      \
        }                                                                      \
        float prev3 = __shfl_up_sync(FULLMASK, la3, 1);                        \
        if (lane == 0) prev3 = NEGINF;                                         \
        const float mloc = fmaxf(fmaxf(la0, la1), fmaxf(la2, la3));            \
        const float m    = fmaxf(mloc, prev3);                                 \
        const float e0 = ex2(la0 - m);                                         \
        const float e1 = ex2(la1 - m);                                         \
        const float e2 = ex2(la2 - m);                                         \
        const float e3 = ex2(la3 - m);                                         \
        const float ep = ex2(prev3 - m);                                       \
        const float s0 = e0 + ep;                                              \
        const float s1 = __fmaf_rn(c1f, ep, e1 + e0);                          \
        const float s2 = e2 + e1;                                              \
        const float s3 = __fmaf_rn(c3f, e1, e3 + e2);                          \
        la0 = lg2(fmaxf(s0, TINYF) * pbe) + m;                                 \
        la1 = lg2(fmaxf(s1, TINYF) * p1e) + m;                                 \
        la2 = lg2(fmaxf(s2, TINYF) * pbe) + m;                                 \
        la3 = lg2(fmaxf(s3, TINYF) * p3e) + m;                                 \
    }

    // main loop: t = 1 .. 508 in groups of 4 (slots 1,2,3,0 statically)
    for (int tb = 1; tb + 3 < T_; tb += 4) {
        CTC_STEP(tb + 0, 1)
        CTC_STEP(tb + 1, 2)
        CTC_STEP(tb + 2, 3)
        CTC_STEP(tb + 3, 0)
    }
    // remainder: t = 509, 510, 511 (slots 1, 2, 3)
    CTC_STEP(509, 1)
    CTC_STEP(510, 2)
    CTC_STEP(511, 3)
#undef CTC_STEP

    // ---- final: loss = -ln2 * log2addexp2(alpha[2*len], alpha[2*len-1]) ----
    int end = 2 * len;
    if (end > S_ - 1) end = S_ - 1;
    int pen = end - 1;
    if (pen < 0) pen = 0;
    // gather alpha[s]: lane s>>2, register s&3 (end/pen uniform per warp)
    const int re = end & 3, rp_ = pen & 3;
    const float ve_all = (re == 0) ? la0 : (re == 1) ? la1 : (re == 2) ? la2 : la3;
    const float vp_all = (rp_ == 0) ? la0 : (rp_ == 1) ? la1 : (rp_ == 2) ? la2 : la3;
    const float ve = __shfl_sync(FULLMASK, ve_all, end >> 2);
    const float vp = __shfl_sync(FULLMASK, vp_all, pen >> 2);
    if (lane == 0) {
        const float m = fmaxf(ve, vp);
        const float d = fabsf(ve - vp);
        const float l2sum = m + lg2(1.f + ex2(-d));   // log2-domain logaddexp
        out[b] = -l2sum * 0.69314718055994530942f;    // nats
    }
}

extern "C" void kernel_launch(void* const* d_in, const int* in_sizes, int n_in,
                              void* d_out, int out_size) {
    const int* y_true;
    const float* y_pred;
    if (in_sizes[0] == B_ * L_) {
        y_true = (const int*)d_in[0];
        y_pred = (const float*)d_in[1];
    } else {
        y_true = (const int*)d_in[1];
        y_pred = (const float*)d_in[0];
    }
    ctc_loss_kernel<<<B_ / WARPS, WARPS * 32>>>(y_true, y_pred, (float*)d_out);
}

// round 15
// speedup vs baseline: 2.1597x; 1.8477x over previous
#include <cuda_runtime.h>
#include <cstdint>

// CTC loss (Keras ctc_batch_cost convention, blank = C-1).
// y_true: [B, L] int32; y_pred: [B, T, C] float32 softmax probs.
// out: [B] float32 = -log P(labels | y_pred).
//
// R15: 4-step windowed-linear recursion (R14) + WAVEFRONT SCALE FIX.
// Per lane: linear v0..v3 + log2 scale m (true log2 alpha = m + lg2 v).
// R14's failure mechanism: dead lanes adopted their neighbor's PRE-adoption
// scale (simultaneous shfl), so lanes <=2 ahead of the live front received
// mass at a stale scale (~5-7 bits early on) -> ~2e-3 rel_err. Fix:
//   - 3-round adoption loop propagates the live frontier scale down dead
//     chains (mass advances <=2 lanes/window; 3 gives margin),
//   - f computed AFTER adoption from the final neighbor scale,
//   - dead lanes force f=1 (exact within adoption reach; harmless beyond,
//     and avoids 0*inf NaN from ex2 of deep stale gaps),
//   - adoption loop skipped (warp-uniform vote) once all lanes are live.
// In-window step is MUFU-free: inc = shfl_up(v3)*f;
//   v0' = (v0+inc)*pb; v1' = (v1+v0+c1*inc)*p1;
//   v2' = (v2+v1)*pb;  v3' = (v3+v2+c3*v1)*p3;   (p's include +eps)
// Register __ldg prefetch ring depth 4; no shared memory.

#define FULLMASK 0xFFFFFFFFu

constexpr int B_ = 256;
constexpr int T_ = 512;
constexpr int C_ = 128;
constexpr int L_ = 48;
constexpr int S_ = 2 * L_ + 1;   // 97
constexpr int WARPS = 4;          // samples per block
constexpr float EPSF  = 1e-7f;
constexpr float TINYF = 1e-37f;

__device__ __forceinline__ float ex2(float x) {
    float r; asm("ex2.approx.f32 %0, %1;" : "=f"(r) : "f"(x)); return r;
}
__device__ __forceinline__ float lg2(float x) {
    float r; asm("lg2.approx.f32 %0, %1;" : "=f"(r) : "f"(x)); return r;
}

__global__ __launch_bounds__(WARPS * 32, 1)
void ctc_loss_kernel(const int* __restrict__ y_true,
                     const float* __restrict__ y_pred,
                     float* __restrict__ out) {
    const int lane = threadIdx.x & 31;
    const int w    = threadIdx.x >> 5;
    const int b    = blockIdx.x * WARPS + w;

    const float* prow = y_pred + (size_t)b * T_ * C_;
    const int*   lab  = y_true + b * L_;
    const int blank = C_ - 1;

    // ---- per-lane static setup (identical to passing R13) ----
    const int k1 = 2 * lane;
    const int k3 = 2 * lane + 1;
    const int lab1  = (k1 < L_) ? lab[k1] : blank;
    const int lab3  = (k3 < L_) ? lab[k3] : blank;
    const int labm1 = (k1 >= 1 && k1 - 1 < L_) ? lab[k1 - 1] : blank;
    const int cls1 = lab1 & (C_ - 1);
    const int cls3 = lab3 & (C_ - 1);
    const float c1f = ((lab1 != blank) && (lane == 0 || lab1 != labm1)) ? 1.f : 0.f;
    const float c3f = ((lab3 != blank) && (lab3 != lab1)) ? 1.f : 0.f;

    const unsigned bl0 = __ballot_sync(FULLMASK, lab[lane] != 0);
    const unsigned bl1 = __ballot_sync(FULLMASK,
                          (lane + 32 < L_) ? (lab[lane + 32] != 0) : false);
    const int len = __popc(bl0) + __popc(bl1);

    // ---- t = 0 init: linear values, scale m = 0 ----
    float v0 = 0.f, v1 = 0.f, v2 = 0.f, v3 = 0.f;
    if (lane == 0) {
        v0 = __ldg(prow + blank) + EPSF;
        v1 = __ldg(prow + cls1)  + EPSF;
    }
    float m = 0.f;   // per-lane log2 scale
    float f = 0.f;   // cross-lane conversion factor (lane0: always 0)

    // ---- register prefetch ring, depth 4 ----
    float pbr[4], p1r[4], p3r[4];
    #pragma unroll
    for (int i = 1; i <= 4; ++i) {
        const float* r = prow + (size_t)i * C_;
        pbr[i & 3] = __ldg(r + blank);
        p1r[i & 3] = __ldg(r + cls1);
        p3r[i & 3] = __ldg(r + cls3);
    }

#define CTC_BOUNDARY()                                                         \
    {                                                                          \
        const float mx = fmaxf(fmaxf(v0, v1), fmaxf(v2, v3));                  \
        const bool active = (mx > TINYF);                                      \
        if (active) {                                                          \
            const float inv = __fdividef(1.f, mx);                             \
            v0 *= inv; v1 *= inv; v2 *= inv; v3 *= inv;                        \
            m += lg2(mx);                                                      \
        } else {                                                               \
            v0 = v1 = v2 = v3 = 0.f;                                           \
        }                                                                      \
        if (!__all_sync(FULLMASK, active)) {                                   \
            /* wavefront: propagate live scale down dead chains (<=3 hops) */  \
            _Pragma("unroll")                                                  \
            for (int r_ = 0; r_ < 3; ++r_) {                                   \
                const float ma_ = __shfl_up_sync(FULLMASK, m, 1);              \
                if (lane > 0 && !active) m = ma_;                              \
            }                                                                  \
        }                                                                      \
        const float mp_ = __shfl_up_sync(FULLMASK, m, 1);                      \
        if (lane == 0)    f = 0.f;                                             \
        else if (active)  f = fminf(ex2(mp_ - m), 1e37f);                      \
        else              f = 1.f;  /* adopted => mp_==m; also no-NaN guard */ \
    }

#define CTC_STEP(T_IDX, SLOT)                                                  \
    {                                                                          \
        const float pbe = pbr[SLOT] + EPSF;                                    \
        const float p1e = p1r[SLOT] + EPSF;                                    \
        const float p3e = p3r[SLOT] + EPSF;                                    \
        if ((T_IDX) + 4 < T_) {                                                \
            const float* rp = prow + (size_t)((T_IDX) + 4) * C_;               \
            pbr[SLOT] = __ldg(rp + blank);                                     \
            p1r[SLOT] = __ldg(rp + cls1);                                      \
            p3r[SLOT] = __ldg(rp + cls3);                                      \
        }                                                                      \
        const float v3p = __shfl_up_sync(FULLMASK, v3, 1);                     \
        const float inc = v3p * f;                                             \
        const float s0 = v0 + inc;                                             \
        const float s1 = __fmaf_rn(c1f, inc, v1 + v0);                         \
        const float s2 = v2 + v1;                                              \
        const float s3 = __fmaf_rn(c3f, v1, v3 + v2);                          \
        v0 = s0 * pbe; v1 = s1 * p1e; v2 = s2 * pbe; v3 = s3 * p3e;            \
    }

    // main loop: windows of 4 steps, t = 1 .. 508 (slots 1,2,3,0 statically)
    for (int tb = 1; tb + 3 < T_; tb += 4) {
        CTC_BOUNDARY()
        CTC_STEP(tb + 0, 1)
        CTC_STEP(tb + 1, 2)
        CTC_STEP(tb + 2, 3)
        CTC_STEP(tb + 3, 0)
    }
    // remainder window: t = 509, 510, 511
    CTC_BOUNDARY()
    CTC_STEP(509, 1)
    CTC_STEP(510, 2)
    CTC_STEP(511, 3)
#undef CTC_BOUNDARY
#undef CTC_STEP

    // ---- final: loss = -ln2 * log2addexp2(m+lg2 v[end], m+lg2 v[pen]) ----
    int end = 2 * len;
    if (end > S_ - 1) end = S_ - 1;
    int pen = end - 1;
    if (pen < 0) pen = 0;
    const int re = end & 3, rp_ = pen & 3;
    const float ve_all = (re == 0) ? v0 : (re == 1) ? v1 : (re == 2) ? v2 : v3;
    const float vp_all = (rp_ == 0) ? v0 : (rp_ == 1) ? v1 : (rp_ == 2) ? v2 : v3;
    const float ve  = __shfl_sync(FULLMASK, ve_all, end >> 2);
    const float me  = __shfl_sync(FULLMASK, m,      end >> 2);
    const float vp  = __shfl_sync(FULLMASK, vp_all, pen >> 2);
    const float mpn = __shfl_sync(FULLMASK, m,      pen >> 2);
    if (lane == 0) {
        const float l1 = me  + lg2(fmaxf(ve, 1e-37f));
        const float l2 = mpn + lg2(fmaxf(vp, 1e-37f));
        const float mm = fmaxf(l1, l2);
        const float d  = fabsf(l1 - l2);
        const float l2sum = mm + lg2(1.f + ex2(-d));
        out[b] = -l2sum * 0.69314718055994530942f;   // nats
    }
}

extern "C" void kernel_launch(void* const* d_in, const int* in_sizes, int n_in,
                              void* d_out, int out_size) {
    const int* y_true;
    const float* y_pred;
    if (in_sizes[0] == B_ * L_) {
        y_true = (const int*)d_in[0];
        y_pred = (const float*)d_in[1];
    } else {
        y_true = (const int*)d_in[1];
        y_pred = (const float*)d_in[0];
    }
    ctc_loss_kernel<<<B_ / WARPS, WARPS * 32>>>(y_true, y_pred, (float*)d_out);
}

// round 17
// speedup vs baseline: 2.7107x; 1.2552x over previous
#include <cuda_runtime.h>
#include <cstdint>

// CTC loss (Keras ctc_batch_cost convention, blank = C-1).
// y_true: [B, L] int32; y_pred: [B, T, C] float32 softmax probs.
// out: [B] float32 = -log P(labels | y_pred).
//
// R17 = resubmission of R16 (broker infra failed twice; never ran).
// R15 (windowed-linear, wavefront-safe scales) + two chain cuts:
//  (1) 2-TIMESTEP FUSION: one set of parallel shuffles (u1,u2,u3,q3p) serves
//      two recursion steps; prev lane's post-stepA top state is reconstructed
//      locally: u3A = (u3 + u2 + c3p*u1) * q3p. Halves serial shfl count.
//  (2) EXACT POWER-OF-2 BOUNDARIES: m is an int exponent; normalization
//      v *= 2^-e and transfer f = 2^(mp-m) are bit-constructed (exact, no
//      MUFU, no rounding). Invariant true_log2(alpha) = m + lg2(v).
// Register __ldg prefetch ring depth 8; no shared memory.

#define FULLMASK 0xFFFFFFFFu

constexpr int B_ = 256;
constexpr int T_ = 512;
constexpr int C_ = 128;
constexpr int L_ = 48;
constexpr int S_ = 2 * L_ + 1;   // 97
constexpr int WARPS = 4;          // samples per block
constexpr float EPSF  = 1e-7f;
constexpr float TINYF = 1e-37f;

__device__ __forceinline__ float ex2(float x) {
    float r; asm("ex2.approx.f32 %0, %1;" : "=f"(r) : "f"(x)); return r;
}
__device__ __forceinline__ float lg2(float x) {
    float r; asm("lg2.approx.f32 %0, %1;" : "=f"(r) : "f"(x)); return r;
}
// exact 2^k for k in [-126, 127]
__device__ __forceinline__ float pow2i(int k) {
    return __int_as_float((k + 127) << 23);
}

__global__ __launch_bounds__(WARPS * 32, 1)
void ctc_loss_kernel(const int* __restrict__ y_true,
                     const float* __restrict__ y_pred,
                     float* __restrict__ out) {
    const int lane = threadIdx.x & 31;
    const int w    = threadIdx.x >> 5;
    const int b    = blockIdx.x * WARPS + w;

    const float* prow = y_pred + (size_t)b * T_ * C_;
    const int*   lab  = y_true + b * L_;
    const int blank = C_ - 1;

    // ---- per-lane static setup (same mapping as passing R13/R15) ----
    const int k1 = 2 * lane;
    const int k3 = 2 * lane + 1;
    const int lab1  = (k1 < L_) ? lab[k1] : blank;
    const int lab3  = (k3 < L_) ? lab[k3] : blank;
    const int labm1 = (k1 >= 1 && k1 - 1 < L_) ? lab[k1 - 1] : blank;
    const int cls1 = lab1 & (C_ - 1);
    const int cls3 = lab3 & (C_ - 1);
    const float c1f = ((lab1 != blank) && (lane == 0 || lab1 != labm1)) ? 1.f : 0.f;
    const float c3f = ((lab3 != blank) && (lab3 != lab1)) ? 1.f : 0.f;
    // prev lane's c3 flag (for fused reconstruction); lane 0 value unused (f=0)
    const float c3p = __shfl_up_sync(FULLMASK, c3f, 1);

    const unsigned bl0 = __ballot_sync(FULLMASK, lab[lane] != 0);
    const unsigned bl1 = __ballot_sync(FULLMASK,
                          (lane + 32 < L_) ? (lab[lane + 32] != 0) : false);
    const int len = __popc(bl0) + __popc(bl1);

    // ---- t = 0 init: linear values, integer log2 scale m = 0 ----
    float v0 = 0.f, v1 = 0.f, v2 = 0.f, v3 = 0.f;
    if (lane == 0) {
        v0 = __ldg(prow + blank) + EPSF;
        v1 = __ldg(prow + cls1)  + EPSF;
    }
    int   m = 0;     // per-lane scale: true log2 alpha = m + lg2(v)
    float f = 0.f;   // cross-lane conversion factor (lane0: always 0)

    // ---- register prefetch ring, depth 8 (rows t, slot = t & 7) ----
    float pbr[8], p1r[8], p3r[8];
    #pragma unroll
    for (int i = 1; i <= 8; ++i) {
        const float* r = prow + (size_t)i * C_;
        pbr[i & 7] = __ldg(r + blank);
        p1r[i & 7] = __ldg(r + cls1);
        p3r[i & 7] = __ldg(r + cls3);
    }

    // window boundary: exact power-of-2 normalization + transfer factor
#define CTC_BOUNDARY()                                                         \
    {                                                                          \
        const float mx = fmaxf(fmaxf(v0, v1), fmaxf(v2, v3));                  \
        const bool active = (mx > TINYF);                                      \
        if (active) {                                                          \
            int e = ((__float_as_int(mx) >> 23) & 0xFF) - 127;                 \
            e = max(-126, min(126, e));                                        \
            const float scl = pow2i(-e);       /* exact 2^-e */                \
            v0 *= scl; v1 *= scl; v2 *= scl; v3 *= scl;                        \
            m += e;                                                            \
        } else {                                                               \
            v0 = v1 = v2 = v3 = 0.f;                                           \
        }                                                                      \
        if (!__all_sync(FULLMASK, active)) {                                   \
            /* wavefront: propagate live scale down dead chains (<=3 hops) */  \
            _Pragma("unroll")                                                  \
            for (int r_ = 0; r_ < 3; ++r_) {                                   \
                const int ma_ = __shfl_up_sync(FULLMASK, m, 1);                \
                if (lane > 0 && !active) m = ma_;                              \
            }                                                                  \
        }                                                                      \
        const int mp_ = __shfl_up_sync(FULLMASK, m, 1);                        \
        if (lane == 0)    f = 0.f;                                             \
        else if (active)  f = pow2i(max(-126, min(126, mp_ - m)));             \
        else              f = 1.f;  /* adopted => mp_ == m */                  \
    }

    // fused 2-timestep update: timesteps TA (slot SA) and TA+1 (slot SB)
#define CTC_FUSE(TA, SA, SB)                                                   \
    {                                                                          \
        const float qbA = pbr[SA] + EPSF;                                      \
        const float q1A = p1r[SA] + EPSF;                                      \
        const float q3A = p3r[SA] + EPSF;                                      \
        const float qbB = pbr[SB] + EPSF;                                      \
        const float q1B = p1r[SB] + EPSF;                                      \
        const float q3B = p3r[SB] + EPSF;                                      \
        if ((TA) + 8 < T_) {                                                   \
            const float* rA = prow + (size_t)((TA) + 8) * C_;                  \
            pbr[SA] = __ldg(rA + blank);                                       \
            p1r[SA] = __ldg(rA + cls1);                                        \
            p3r[SA] = __ldg(rA + cls3);                                        \
        }                                                                      \
        if ((TA) + 9 < T_) {                                                   \
            const float* rB = prow + (size_t)((TA) + 9) * C_;                  \
            pbr[SB] = __ldg(rB + blank);                                       \
            p1r[SB] = __ldg(rB + cls1);                                        \
            p3r[SB] = __ldg(rB + cls3);                                        \
        }                                                                      \
        const float u1  = __shfl_up_sync(FULLMASK, v1, 1);                     \
        const float u2  = __shfl_up_sync(FULLMASK, v2, 1);                     \
        const float u3  = __shfl_up_sync(FULLMASK, v3, 1);                     \
        const float q3p = __shfl_up_sync(FULLMASK, q3A, 1);                    \
        const float incA = f * u3;                                             \
        const float w0 = (v0 + incA)                    * qbA;                 \
        const float w1 = __fmaf_rn(c1f, incA, v1 + v0)  * q1A;                 \
        const float w2 = (v2 + v1)                      * qbA;                 \
        const float w3 = __fmaf_rn(c3f, v1, v3 + v2)    * q3A;                 \
        const float u3A = __fmaf_rn(c3p, u1, u3 + u2)   * q3p;                 \
        const float incB = f * u3A;                                            \
        v0 = (w0 + incB)                    * qbB;                             \
        v1 = __fmaf_rn(c1f, incB, w1 + w0)  * q1B;                             \
        v2 = (w2 + w1)                      * qbB;                             \
        v3 = __fmaf_rn(c3f, w1, w3 + w2)    * q3B;                             \
    }

    // single (non-fused) step for the odd tail
#define CTC_STEP1(T_IDX, SLOT)                                                 \
    {                                                                          \
        const float qb = pbr[SLOT] + EPSF;                                     \
        const float q1 = p1r[SLOT] + EPSF;                                     \
        const float q3 = p3r[SLOT] + EPSF;                                     \
        const float u3 = __shfl_up_sync(FULLMASK, v3, 1);                      \
        const float inc = f * u3;                                              \
        const float s0 = v0 + inc;                                             \
        const float s1 = __fmaf_rn(c1f, inc, v1 + v0);                         \
        const float s2 = v2 + v1;                                              \
        const float s3 = __fmaf_rn(c3f, v1, v3 + v2);                          \
        v0 = s0 * qb; v1 = s1 * q1; v2 = s2 * qb; v3 = s3 * q3;                \
    }

    // main loop: bodies of 8 steps = 2 windows = 4 fused iters
    // steps 1..504 in 63 bodies; slots (t & 7) are static per position.
    for (int tb = 1; tb <= 497; tb += 8) {
        CTC_BOUNDARY()
        CTC_FUSE(tb + 0, 1, 2)
        CTC_FUSE(tb + 2, 3, 4)
        CTC_BOUNDARY()
        CTC_FUSE(tb + 4, 5, 6)
        CTC_FUSE(tb + 6, 7, 0)
    }
    // remainder: t = 505..511
    CTC_BOUNDARY()
    CTC_FUSE(505, 1, 2)
    CTC_FUSE(507, 3, 4)
    CTC_BOUNDARY()
    CTC_FUSE(509, 5, 6)
    CTC_STEP1(511, 7)
#undef CTC_BOUNDARY
#undef CTC_FUSE
#undef CTC_STEP1

    // ---- final: loss = -ln2 * log2addexp2(m+lg2 v[end], m+lg2 v[pen]) ----
    int end = 2 * len;
    if (end > S_ - 1) end = S_ - 1;
    int pen = end - 1;
    if (pen < 0) pen = 0;
    const int re = end & 3, rp_ = pen & 3;
    const float ve_all = (re == 0) ? v0 : (re == 1) ? v1 : (re == 2) ? v2 : v3;
    const float vp_all = (rp_ == 0) ? v0 : (rp_ == 1) ? v1 : (rp_ == 2) ? v2 : v3;
    const float ve  = __shfl_sync(FULLMASK, ve_all, end >> 2);
    const int   me  = __shfl_sync(FULLMASK, m,      end >> 2);
    const float vp  = __shfl_sync(FULLMASK, vp_all, pen >> 2);
    const int   mpn = __shfl_sync(FULLMASK, m,      pen >> 2);
    if (lane == 0) {
        const float l1 = (float)me  + lg2(fmaxf(ve, 1e-37f));
        const float l2 = (float)mpn + lg2(fmaxf(vp, 1e-37f));
        const float mm = fmaxf(l1, l2);
        const float d  = fabsf(l1 - l2);
        const float l2sum = mm + lg2(1.f + ex2(-d));
        out[b] = -l2sum * 0.69314718055994530942f;   // nats
    }
}

extern "C" void kernel_launch(void* const* d_in, const int* in_sizes, int n_in,
                              void* d_out, int out_size) {
    const int* y_true;
    const float* y_pred;
    if (in_sizes[0] == B_ * L_) {
        y_true = (const int*)d_in[0];
        y_pred = (const float*)d_in[1];
    } else {
        y_true = (const int*)d_in[1];
        y_pred = (const float*)d_in[0];
    }
    ctc_loss_kernel<<<B_ / WARPS, WARPS * 32>>>(y_true, y_pred, (float*)d_out);
}